// round 6
// baseline (speedup 1.0000x reference)
#include <cuda_runtime.h>
#include <cuda_fp16.h>
#include <math.h>

#define NN 10000
#define EE 320000
#define FIN 128
#define HC 256
#define NH1 16
#define NC1 16
#define GG 64
#define LL 10

typedef unsigned long long u64;

// ---------------- scratch ----------------------------------------------------
__device__ __half g_h1h[NN * HC];    // layer1 features (fp16 gather copy)
__device__ __half g_h2h[NN * HC];    // layer2 features (fp16 gather copy)
__device__ float g_out1[NN * HC];    // layer1 aggregated output (fp32)
__device__ float g_als1[NN * NH1];
__device__ float g_ald1[NN * NH1];
__device__ float g_als2[NN];
__device__ float g_ald2[NN];
__device__ float g_sums[GG * HC];
__device__ float g_cnts[GG];
__device__ int   g_rowptr[NN + 1];
__device__ int   g_deg[NN];          // histogram -> start-offset cursor
__device__ int   g_csr_src[EE];

__device__ __forceinline__ float leaky(float v) { return v >= 0.f ? v : 0.2f * v; }

__device__ __forceinline__ void redAdd4(float4* addr, float4 v) {
    asm volatile("red.global.add.v4.f32 [%0], {%1, %2, %3, %4};"
                 :: "l"(addr), "f"(v.x), "f"(v.y), "f"(v.z), "f"(v.w) : "memory");
}

__device__ __forceinline__ u64 packdup(float w) {
    u64 r; asm("mov.b64 %0, {%1, %1};" : "=l"(r) : "f"(w)); return r;
}
__device__ __forceinline__ void fma2(u64& acc, u64 x, u64 w) {
    asm("fma.rn.f32x2 %0, %1, %2, %0;" : "+l"(acc) : "l"(x), "l"(w));
}
__device__ __forceinline__ float2 unpack2(u64 v) {
    float lo, hi; asm("mov.b64 {%0, %1}, %2;" : "=f"(lo), "=f"(hi) : "l"(v));
    return make_float2(lo, hi);
}

// ---------------- init kernels -------------------------------------------------
__global__ void init_side_k() {
    int i = blockIdx.x * blockDim.x + threadIdx.x;
    if (i < NN) g_deg[i] = 0;
    if (i < GG * HC) g_sums[i] = 0.f;
    if (i < GG) g_cnts[i] = 0.f;
}

// ---------------- CSR build ---------------------------------------------------
__global__ void csr_count(const int* __restrict__ dst) {
    int i = blockIdx.x * blockDim.x + threadIdx.x;
    if (i * 4 >= EE) return;
    int4 d4 = ((const int4*)dst)[i];
    atomicAdd(&g_deg[d4.x], 1);
    atomicAdd(&g_deg[d4.y], 1);
    atomicAdd(&g_deg[d4.z], 1);
    atomicAdd(&g_deg[d4.w], 1);
}

__global__ void csr_scan() {                          // 1024 threads, 1 block
    __shared__ int part[1024];
    const int CH = 10;
    int t = threadIdx.x;
    int base = t * CH;
    int s = 0;
#pragma unroll
    for (int j = 0; j < CH; j++) { int idx = base + j; if (idx < NN) s += g_deg[idx]; }
    part[t] = s;
    __syncthreads();
    for (int o = 1; o < 1024; o <<= 1) {
        int v = (t >= o) ? part[t - o] : 0;
        __syncthreads();
        part[t] += v;
        __syncthreads();
    }
    int run = (t == 0) ? 0 : part[t - 1];
#pragma unroll
    for (int j = 0; j < CH; j++) {
        int idx = base + j;
        if (idx < NN) {
            g_rowptr[idx] = run;
            int dg = g_deg[idx];
            g_deg[idx] = run;                         // becomes write cursor
            run += dg;
            if (idx == NN - 1) g_rowptr[NN] = run;
        }
    }
}

__global__ void csr_fill(const int* __restrict__ src, const int* __restrict__ dst) {
    int i = blockIdx.x * blockDim.x + threadIdx.x;
    if (i * 4 >= EE) return;
    int4 s4 = ((const int4*)src)[i];
    int4 d4 = ((const int4*)dst)[i];
    g_csr_src[atomicAdd(&g_deg[d4.x], 1)] = s4.x;
    g_csr_src[atomicAdd(&g_deg[d4.y], 1)] = s4.y;
    g_csr_src[atomicAdd(&g_deg[d4.z], 1)] = s4.z;
    g_csr_src[atomicAdd(&g_deg[d4.w], 1)] = s4.w;
}

// ---------------- GEMM + fused logits + fp16 store ---------------------------
template <int LAYER>
__global__ void __launch_bounds__(256) gemm_k(const float* __restrict__ Xin,
                       const float* __restrict__ W,
                       const float* __restrict__ bin,
                       const float* __restrict__ a_src,
                       const float* __restrict__ a_dst) {
    constexpr int K = (LAYER == 1) ? FIN : HC;
    const float* __restrict__ X = (LAYER == 1) ? Xin : g_out1;
    __half* __restrict__ Hout = (LAYER == 1) ? g_h1h : g_h2h;

    __shared__ u64 xst[K * 16];             // [k][row_pair]
    __shared__ float red[8][64];            // layer-2 logit reduction
    float* xs = (float*)xst;

    int row0 = blockIdx.x * 32;
    int col = threadIdx.x;

    for (int i = threadIdx.x; i < 32 * K; i += 256) {
        int r = i & 31, k = i >> 5;
        int row = row0 + r;
        float v = 0.f;
        if (row < NN) {
            v = X[(size_t)row * K + k];
            if (LAYER == 2) v = fmaxf(v + bin[k], 0.f);
        }
        xs[k * 32 + r] = v;
    }
    __syncthreads();

    u64 acc[16];
#pragma unroll
    for (int p = 0; p < 16; p++) acc[p] = 0ull;

#pragma unroll 2
    for (int k = 0; k < K; k++) {
        u64 wp = packdup(W[k * HC + col]);
        const ulonglong2* xp2 = (const ulonglong2*)(xst + k * 16);
#pragma unroll
        for (int p = 0; p < 8; p++) {
            ulonglong2 v = xp2[p];
            fma2(acc[2 * p], v.x, wp);
            fma2(acc[2 * p + 1], v.y, wp);
        }
    }

    float As = a_src[col], Ad = a_dst[col];

#pragma unroll
    for (int p = 0; p < 16; p++) {
        float2 lh = unpack2(acc[p]);
        int r0 = row0 + 2 * p;
        if (r0 < NN)     Hout[(size_t)r0 * HC + col] = __float2half_rn(lh.x);
        if (r0 + 1 < NN) Hout[(size_t)(r0 + 1) * HC + col] = __float2half_rn(lh.y);

        float vs0 = lh.x * As, vd0 = lh.x * Ad;
        float vs1 = lh.y * As, vd1 = lh.y * Ad;

        if (LAYER == 1) {
#pragma unroll
            for (int o = 1; o < 16; o <<= 1) {
                vs0 += __shfl_xor_sync(0xffffffffu, vs0, o);
                vd0 += __shfl_xor_sync(0xffffffffu, vd0, o);
                vs1 += __shfl_xor_sync(0xffffffffu, vs1, o);
                vd1 += __shfl_xor_sync(0xffffffffu, vd1, o);
            }
            if ((col & 15) == 0) {
                int head = col >> 4;
                if (r0 < NN)     { g_als1[r0 * NH1 + head] = vs0; g_ald1[r0 * NH1 + head] = vd0; }
                if (r0 + 1 < NN) { g_als1[(r0 + 1) * NH1 + head] = vs1; g_ald1[(r0 + 1) * NH1 + head] = vd1; }
            }
        } else {
#pragma unroll
            for (int o = 1; o < 32; o <<= 1) {
                vs0 += __shfl_xor_sync(0xffffffffu, vs0, o);
                vd0 += __shfl_xor_sync(0xffffffffu, vd0, o);
                vs1 += __shfl_xor_sync(0xffffffffu, vs1, o);
                vd1 += __shfl_xor_sync(0xffffffffu, vd1, o);
            }
            if ((col & 31) == 0) {
                int w = col >> 5;
                red[w][p * 4 + 0] = vs0;
                red[w][p * 4 + 1] = vd0;
                red[w][p * 4 + 2] = vs1;
                red[w][p * 4 + 3] = vd1;
            }
        }
    }

    if (LAYER == 2) {
        __syncthreads();
        if (threadIdx.x < 64) {
            int t = threadIdx.x;
            float s = 0.f;
#pragma unroll
            for (int w = 0; w < 8; w++) s += red[w][t];
            int p = t >> 2, q = t & 3;
            int r = row0 + 2 * p + (q >> 1);
            if (r < NN) {
                if ((q & 1) == 0) g_als2[r] = s;
                else              g_ald2[r] = s;
            }
        }
    }
}

// ---------------- fused GAT layer 1: 2 warps per dst (edge split) -------------
// block = 256 threads = 8 warps = 4 dsts. half-1 warp dumps partials to smem.
__global__ void __launch_bounds__(256) gat1_k() {
    __shared__ float s_acc[4][HC];
    __shared__ float s_sum[4][32];

    int gw = (blockIdx.x * blockDim.x + threadIdx.x) >> 5;
    int lane = threadIdx.x & 31;
    int d = gw >> 1;
    int half = gw & 1;
    int pair = (threadIdx.x >> 5) >> 1;
    const int hh = lane >> 1;            // head of this lane's 8 channels

    float ald_h = g_ald1[d * NH1 + hh];
    float ssum = 0.f;
    float acc[8] = {0.f, 0.f, 0.f, 0.f, 0.f, 0.f, 0.f, 0.f};

    if (half == 0) {
        float wself = __expf(leaky(g_als1[d * NH1 + hh] + ald_h));
        ssum = wself;
        uint4 q = *((const uint4*)(g_h1h + (size_t)d * HC) + lane);
        const __half2* h2 = (const __half2*)&q;
#pragma unroll
        for (int k = 0; k < 4; k++) {
            float2 f = __half22float2(h2[k]);
            acc[2 * k] = wself * f.x;
            acc[2 * k + 1] = wself * f.y;
        }
    }

    int beg = g_rowptr[d], end = g_rowptr[d + 1];

#define GAT1_STEP(SRC)                                                          \
    {                                                                           \
        int s_ = (SRC);                                                         \
        float we = __expf(leaky(g_als1[s_ * NH1 + hh] + ald_h));                \
        ssum += we;                                                             \
        uint4 q = *((const uint4*)(g_h1h + (size_t)s_ * HC) + lane);            \
        const __half2* h2 = (const __half2*)&q;                                 \
        _Pragma("unroll")                                                       \
        for (int k = 0; k < 4; k++) {                                           \
            float2 f = __half22float2(h2[k]);                                   \
            acc[2 * k]     = fmaf(we, f.x, acc[2 * k]);                         \
            acc[2 * k + 1] = fmaf(we, f.y, acc[2 * k + 1]);                     \
        }                                                                       \
    }

    for (int base = beg + half * 32; base < end; base += 64) {
        int idx = base + lane;
        int sv = (idx < end) ? g_csr_src[idx] : 0;
        int n = min(32, end - base);
        if (n == 32) {
#pragma unroll 8
            for (int j = 0; j < 32; j++) GAT1_STEP(__shfl_sync(0xffffffffu, sv, j));
        } else {
            for (int j = 0; j < n; j++) GAT1_STEP(__shfl_sync(0xffffffffu, sv, j));
        }
    }

    if (half == 1) {
        float* sa = s_acc[pair] + 8 * lane;
#pragma unroll
        for (int j = 0; j < 8; j++) sa[j] = acc[j];
        s_sum[pair][lane] = ssum;
    }
    __syncthreads();
    if (half == 0) {
        ssum += s_sum[pair][lane];
        const float* sa = s_acc[pair] + 8 * lane;
#pragma unroll
        for (int j = 0; j < 8; j++) acc[j] += sa[j];
        float inv = 1.f / ssum;
        float4* od = (float4*)(g_out1 + (size_t)d * HC) + 2 * lane;
        od[0] = make_float4(acc[0] * inv, acc[1] * inv, acc[2] * inv, acc[3] * inv);
        od[1] = make_float4(acc[4] * inv, acc[5] * inv, acc[6] * inv, acc[7] * inv);
    }
}

// ---------------- fused GAT layer 2: 2 warps per dst + mean-pool red ----------
__global__ void __launch_bounds__(256) gat2_k(const int* __restrict__ batch) {
    __shared__ float s_acc[4][HC];
    __shared__ float s_sum[4][32];

    int gw = (blockIdx.x * blockDim.x + threadIdx.x) >> 5;
    int lane = threadIdx.x & 31;
    int d = gw >> 1;
    int half = gw & 1;
    int pair = (threadIdx.x >> 5) >> 1;

    float ald_d = g_ald2[d];
    float ssum = 0.f;
    float acc[8] = {0.f, 0.f, 0.f, 0.f, 0.f, 0.f, 0.f, 0.f};

    if (half == 0) {
        float wself = __expf(leaky(g_als2[d] + ald_d));
        ssum = wself;
        uint4 q = *((const uint4*)(g_h2h + (size_t)d * HC) + lane);
        const __half2* h2 = (const __half2*)&q;
#pragma unroll
        for (int k = 0; k < 4; k++) {
            float2 f = __half22float2(h2[k]);
            acc[2 * k] = wself * f.x;
            acc[2 * k + 1] = wself * f.y;
        }
    }

    int beg = g_rowptr[d], end = g_rowptr[d + 1];

#define GAT2_STEP(SRC)                                                          \
    {                                                                           \
        int s_ = (SRC);                                                         \
        float we = __expf(leaky(g_als2[s_] + ald_d));                           \
        ssum += we;                                                             \
        uint4 q = *((const uint4*)(g_h2h + (size_t)s_ * HC) + lane);            \
        const __half2* h2 = (const __half2*)&q;                                 \
        _Pragma("unroll")                                                       \
        for (int k = 0; k < 4; k++) {                                           \
            float2 f = __half22float2(h2[k]);                                   \
            acc[2 * k]     = fmaf(we, f.x, acc[2 * k]);                         \
            acc[2 * k + 1] = fmaf(we, f.y, acc[2 * k + 1]);                     \
        }                                                                       \
    }

    for (int base = beg + half * 32; base < end; base += 64) {
        int idx = base + lane;
        int sv = (idx < end) ? g_csr_src[idx] : 0;
        int n = min(32, end - base);
        if (n == 32) {
#pragma unroll 8
            for (int j = 0; j < 32; j++) GAT2_STEP(__shfl_sync(0xffffffffu, sv, j));
        } else {
            for (int j = 0; j < n; j++) GAT2_STEP(__shfl_sync(0xffffffffu, sv, j));
        }
    }

    if (half == 1) {
        float* sa = s_acc[pair] + 8 * lane;
#pragma unroll
        for (int j = 0; j < 8; j++) sa[j] = acc[j];
        s_sum[pair][lane] = ssum;
    }
    __syncthreads();
    if (half == 0) {
        ssum += s_sum[pair][lane];
        const float* sa = s_acc[pair] + 8 * lane;
#pragma unroll
        for (int j = 0; j < 8; j++) acc[j] += sa[j];
        float inv = 1.f / ssum;
        int g = batch[d];
        float4* sd = (float4*)(g_sums + g * HC) + 2 * lane;
        redAdd4(sd,     make_float4(acc[0] * inv, acc[1] * inv, acc[2] * inv, acc[3] * inv));
        redAdd4(sd + 1, make_float4(acc[4] * inv, acc[5] * inv, acc[6] * inv, acc[7] * inv));
        if (lane == 0) atomicAdd(&g_cnts[g], 1.f);
    }
}

// ---------------- final: (mean + b2) @ lin_w + lin_b --------------------------
__global__ void final_k(const float* __restrict__ b2,
                        const float* __restrict__ lw,
                        const float* __restrict__ lb,
                        float* __restrict__ out) {
    __shared__ float p[HC];
    int g = blockIdx.x;
    float cnt = fmaxf(g_cnts[g], 1.f);
    p[threadIdx.x] = g_sums[g * HC + threadIdx.x] / cnt + b2[threadIdx.x];
    __syncthreads();
    if (threadIdx.x < LL) {
        float acc = lb[threadIdx.x];
#pragma unroll 8
        for (int d = 0; d < HC; d++)
            acc = fmaf(p[d], lw[d * LL + threadIdx.x], acc);
        out[g * LL + threadIdx.x] = acc;
    }
}

// ---------------- launch -------------------------------------------------------
extern "C" void kernel_launch(void* const* d_in, const int* in_sizes, int n_in,
                              void* d_out, int out_size) {
    const float* x      = (const float*)d_in[0];
    const int*   ei     = (const int*)d_in[1];
    const int*   batch  = (const int*)d_in[2];
    const float* W1     = (const float*)d_in[3];
    const float* a_src1 = (const float*)d_in[4];
    const float* a_dst1 = (const float*)d_in[5];
    const float* b1     = (const float*)d_in[6];
    const float* W2     = (const float*)d_in[7];
    const float* a_src2 = (const float*)d_in[8];
    const float* a_dst2 = (const float*)d_in[9];
    const float* b2     = (const float*)d_in[10];
    const float* lin_w  = (const float*)d_in[11];
    const float* lin_b  = (const float*)d_in[12];
    float* out = (float*)d_out;

    const int* src = ei;
    const int* dst = ei + EE;

    static cudaStream_t s_csr = nullptr;
    static cudaEvent_t ev_fork = nullptr, ev_csr = nullptr;
    if (!s_csr) {
        cudaStreamCreateWithFlags(&s_csr, cudaStreamNonBlocking);
        cudaEventCreateWithFlags(&ev_fork, cudaEventDisableTiming);
        cudaEventCreateWithFlags(&ev_csr, cudaEventDisableTiming);
    }

    // fork CSR + init pipeline at graph start
    cudaEventRecord(ev_fork, 0);
    cudaStreamWaitEvent(s_csr, ev_fork, 0);
    init_side_k<<<(GG * HC + 255) / 256, 256, 0, s_csr>>>();
    csr_count<<<(EE / 4 + 255) / 256, 256, 0, s_csr>>>(dst);
    csr_scan<<<1, 1024, 0, s_csr>>>();
    csr_fill<<<(EE / 4 + 255) / 256, 256, 0, s_csr>>>(src, dst);
    cudaEventRecord(ev_csr, s_csr);

    // main stream (concurrent): layer-1 GEMM (+fused logits)
    gemm_k<1><<<(NN + 31) / 32, 256>>>(x, W1, nullptr, a_src1, a_dst1);

    // join: gat1 needs CSR
    cudaStreamWaitEvent(0, ev_csr, 0);
    gat1_k<<<(NN * 2 * 32) / 256, 256>>>();

    // layer 2 (relu(out1+b1) folded into gemm2 load; logits fused)
    gemm_k<2><<<(NN + 31) / 32, 256>>>(nullptr, W2, b1, a_src2, a_dst2);
    gat2_k<<<(NN * 2 * 32) / 256, 256>>>(batch);

    final_k<<<GG, 256>>>(b2, lin_w, lin_b, out);
}

// round 7
// speedup vs baseline: 1.0612x; 1.0612x over previous
#include <cuda_runtime.h>
#include <cuda_fp16.h>
#include <math.h>

#define NN 10000
#define EE 320000
#define FIN 128
#define HC 256
#define NH1 16
#define NC1 16
#define GG 64
#define LL 10
#define CAP 256            // per-node adjacency bucket capacity (max deg ~60)

typedef unsigned long long u64;

// ---------------- scratch ----------------------------------------------------
__device__ __half g_h1h[NN * HC];    // layer1 features (fp16 gather copy)
__device__ __half g_h2h[NN * HC];    // layer2 features (fp16 gather copy)
__device__ float g_out1[NN * HC];    // layer1 aggregated output (fp32)
__device__ float g_als1[NN * NH1];
__device__ float g_ald1[NN * NH1];
__device__ float g_als2[NN];
__device__ float g_ald2[NN];
__device__ float g_sums[GG * HC];
__device__ float g_cnts[GG];
__device__ int   g_deg[NN];          // bucket fill cursor / final degree
__device__ int   g_adj[NN * CAP];    // bucketed adjacency (src lists per dst)

__device__ __forceinline__ float leaky(float v) { return v >= 0.f ? v : 0.2f * v; }

__device__ __forceinline__ void redAdd4(float4* addr, float4 v) {
    asm volatile("red.global.add.v4.f32 [%0], {%1, %2, %3, %4};"
                 :: "l"(addr), "f"(v.x), "f"(v.y), "f"(v.z), "f"(v.w) : "memory");
}

__device__ __forceinline__ u64 packdup(float w) {
    u64 r; asm("mov.b64 %0, {%1, %1};" : "=l"(r) : "f"(w)); return r;
}
__device__ __forceinline__ void fma2(u64& acc, u64 x, u64 w) {
    asm("fma.rn.f32x2 %0, %1, %2, %0;" : "+l"(acc) : "l"(x), "l"(w));
}
__device__ __forceinline__ float2 unpack2(u64 v) {
    float lo, hi; asm("mov.b64 {%0, %1}, %2;" : "=f"(lo), "=f"(hi) : "l"(v));
    return make_float2(lo, hi);
}

// ---------------- side-stream init -------------------------------------------
__global__ void init_side_k() {
    int i = blockIdx.x * blockDim.x + threadIdx.x;
    if (i < NN) g_deg[i] = 0;
    if (i < GG * HC) g_sums[i] = 0.f;
    if (i < GG) g_cnts[i] = 0.f;
}

// ---------------- bucketed adjacency fill (no count/scan) ---------------------
__global__ void adj_fill(const int* __restrict__ src, const int* __restrict__ dst) {
    int i = blockIdx.x * blockDim.x + threadIdx.x;
    if (i * 4 >= EE) return;
    int4 s4 = ((const int4*)src)[i];
    int4 d4 = ((const int4*)dst)[i];
    int p;
    p = atomicAdd(&g_deg[d4.x], 1); g_adj[d4.x * CAP + p] = s4.x;
    p = atomicAdd(&g_deg[d4.y], 1); g_adj[d4.y * CAP + p] = s4.y;
    p = atomicAdd(&g_deg[d4.z], 1); g_adj[d4.z * CAP + p] = s4.z;
    p = atomicAdd(&g_deg[d4.w], 1); g_adj[d4.w * CAP + p] = s4.w;
}

// ---------------- GEMM + fused logits + fp16 store ---------------------------
template <int LAYER>
__global__ void __launch_bounds__(256) gemm_k(const float* __restrict__ Xin,
                       const float* __restrict__ W,
                       const float* __restrict__ bin,
                       const float* __restrict__ a_src,
                       const float* __restrict__ a_dst) {
    constexpr int K = (LAYER == 1) ? FIN : HC;
    const float* __restrict__ X = (LAYER == 1) ? Xin : g_out1;
    __half* __restrict__ Hout = (LAYER == 1) ? g_h1h : g_h2h;

    __shared__ u64 xst[K * 16];             // [k][row_pair]
    __shared__ float red[8][64];            // layer-2 logit reduction
    float* xs = (float*)xst;

    int row0 = blockIdx.x * 32;
    int col = threadIdx.x;

    for (int i = threadIdx.x; i < 32 * K; i += 256) {
        int r = i & 31, k = i >> 5;
        int row = row0 + r;
        float v = 0.f;
        if (row < NN) {
            v = X[(size_t)row * K + k];
            if (LAYER == 2) v = fmaxf(v + bin[k], 0.f);
        }
        xs[k * 32 + r] = v;
    }
    __syncthreads();

    u64 acc[16];
#pragma unroll
    for (int p = 0; p < 16; p++) acc[p] = 0ull;

#pragma unroll 2
    for (int k = 0; k < K; k++) {
        u64 wp = packdup(W[k * HC + col]);
        const ulonglong2* xp2 = (const ulonglong2*)(xst + k * 16);
#pragma unroll
        for (int p = 0; p < 8; p++) {
            ulonglong2 v = xp2[p];
            fma2(acc[2 * p], v.x, wp);
            fma2(acc[2 * p + 1], v.y, wp);
        }
    }

    float As = a_src[col], Ad = a_dst[col];

#pragma unroll
    for (int p = 0; p < 16; p++) {
        float2 lh = unpack2(acc[p]);
        int r0 = row0 + 2 * p;
        if (r0 < NN)     Hout[(size_t)r0 * HC + col] = __float2half_rn(lh.x);
        if (r0 + 1 < NN) Hout[(size_t)(r0 + 1) * HC + col] = __float2half_rn(lh.y);

        float vs0 = lh.x * As, vd0 = lh.x * Ad;
        float vs1 = lh.y * As, vd1 = lh.y * Ad;

        if (LAYER == 1) {
#pragma unroll
            for (int o = 1; o < 16; o <<= 1) {
                vs0 += __shfl_xor_sync(0xffffffffu, vs0, o);
                vd0 += __shfl_xor_sync(0xffffffffu, vd0, o);
                vs1 += __shfl_xor_sync(0xffffffffu, vs1, o);
                vd1 += __shfl_xor_sync(0xffffffffu, vd1, o);
            }
            if ((col & 15) == 0) {
                int head = col >> 4;
                if (r0 < NN)     { g_als1[r0 * NH1 + head] = vs0; g_ald1[r0 * NH1 + head] = vd0; }
                if (r0 + 1 < NN) { g_als1[(r0 + 1) * NH1 + head] = vs1; g_ald1[(r0 + 1) * NH1 + head] = vd1; }
            }
        } else {
#pragma unroll
            for (int o = 1; o < 32; o <<= 1) {
                vs0 += __shfl_xor_sync(0xffffffffu, vs0, o);
                vd0 += __shfl_xor_sync(0xffffffffu, vd0, o);
                vs1 += __shfl_xor_sync(0xffffffffu, vs1, o);
                vd1 += __shfl_xor_sync(0xffffffffu, vd1, o);
            }
            if ((col & 31) == 0) {
                int w = col >> 5;
                red[w][p * 4 + 0] = vs0;
                red[w][p * 4 + 1] = vd0;
                red[w][p * 4 + 2] = vs1;
                red[w][p * 4 + 3] = vd1;
            }
        }
    }

    if (LAYER == 2) {
        __syncthreads();
        if (threadIdx.x < 64) {
            int t = threadIdx.x;
            float s = 0.f;
#pragma unroll
            for (int w = 0; w < 8; w++) s += red[w][t];
            int p = t >> 2, q = t & 3;
            int r = row0 + 2 * p + (q >> 1);
            if (r < NN) {
                if ((q & 1) == 0) g_als2[r] = s;
                else              g_ald2[r] = s;
            }
        }
    }
}

// ---------------- fused GAT layer 1 (16 heads), fp16 gather, warp per dst -----
__global__ void __launch_bounds__(256) gat1_k() {
    int w = (blockIdx.x * blockDim.x + threadIdx.x) >> 5;
    int lane = threadIdx.x & 31;
    if (w >= NN) return;
    const int d = w;
    const int hh = lane >> 1;            // 8 channels per lane, head = lane>>1

    float ald_h = g_ald1[d * NH1 + hh];
    float wself = __expf(leaky(g_als1[d * NH1 + hh] + ald_h));
    float ssum = wself;

    float acc[8];
    {
        uint4 q = *((const uint4*)(g_h1h + (size_t)d * HC) + lane);
        const __half2* h2 = (const __half2*)&q;
#pragma unroll
        for (int k = 0; k < 4; k++) {
            float2 f = __half22float2(h2[k]);
            acc[2 * k] = wself * f.x;
            acc[2 * k + 1] = wself * f.y;
        }
    }

    int beg = d * CAP;
    int end = beg + g_deg[d];

#define GAT1_STEP(SRC)                                                          \
    {                                                                           \
        int s_ = (SRC);                                                         \
        float we = __expf(leaky(g_als1[s_ * NH1 + hh] + ald_h));                \
        ssum += we;                                                             \
        uint4 q = *((const uint4*)(g_h1h + (size_t)s_ * HC) + lane);            \
        const __half2* h2 = (const __half2*)&q;                                 \
        _Pragma("unroll")                                                       \
        for (int k = 0; k < 4; k++) {                                           \
            float2 f = __half22float2(h2[k]);                                   \
            acc[2 * k]     = fmaf(we, f.x, acc[2 * k]);                         \
            acc[2 * k + 1] = fmaf(we, f.y, acc[2 * k + 1]);                     \
        }                                                                       \
    }

    for (int base = beg; base < end; base += 32) {
        int idx = base + lane;
        int sv = (idx < end) ? g_adj[idx] : 0;
        int n = min(32, end - base);
        if (n == 32) {
#pragma unroll 8
            for (int j = 0; j < 32; j++) GAT1_STEP(__shfl_sync(0xffffffffu, sv, j));
        } else {
            for (int j = 0; j < n; j++) GAT1_STEP(__shfl_sync(0xffffffffu, sv, j));
        }
    }

    float inv = 1.f / ssum;
    float4* od = (float4*)(g_out1 + (size_t)d * HC) + 2 * lane;
    od[0] = make_float4(acc[0] * inv, acc[1] * inv, acc[2] * inv, acc[3] * inv);
    od[1] = make_float4(acc[4] * inv, acc[5] * inv, acc[6] * inv, acc[7] * inv);
}

// ---------------- fused GAT layer 2 (1 head) + mean-pool red ------------------
__global__ void __launch_bounds__(256) gat2_k(const int* __restrict__ batch) {
    int w = (blockIdx.x * blockDim.x + threadIdx.x) >> 5;
    int lane = threadIdx.x & 31;
    if (w >= NN) return;
    const int d = w;

    float ald_d = g_ald2[d];
    float wself = __expf(leaky(g_als2[d] + ald_d));
    float ssum = wself;

    float acc[8];
    {
        uint4 q = *((const uint4*)(g_h2h + (size_t)d * HC) + lane);
        const __half2* h2 = (const __half2*)&q;
#pragma unroll
        for (int k = 0; k < 4; k++) {
            float2 f = __half22float2(h2[k]);
            acc[2 * k] = wself * f.x;
            acc[2 * k + 1] = wself * f.y;
        }
    }

    int beg = d * CAP;
    int end = beg + g_deg[d];

#define GAT2_STEP(SRC)                                                          \
    {                                                                           \
        int s_ = (SRC);                                                         \
        float we = __expf(leaky(g_als2[s_] + ald_d));                           \
        ssum += we;                                                             \
        uint4 q = *((const uint4*)(g_h2h + (size_t)s_ * HC) + lane);            \
        const __half2* h2 = (const __half2*)&q;                                 \
        _Pragma("unroll")                                                       \
        for (int k = 0; k < 4; k++) {                                           \
            float2 f = __half22float2(h2[k]);                                   \
            acc[2 * k]     = fmaf(we, f.x, acc[2 * k]);                         \
            acc[2 * k + 1] = fmaf(we, f.y, acc[2 * k + 1]);                     \
        }                                                                       \
    }

    for (int base = beg; base < end; base += 32) {
        int idx = base + lane;
        int sv = (idx < end) ? g_adj[idx] : 0;
        int n = min(32, end - base);
        if (n == 32) {
#pragma unroll 8
            for (int j = 0; j < 32; j++) GAT2_STEP(__shfl_sync(0xffffffffu, sv, j));
        } else {
            for (int j = 0; j < n; j++) GAT2_STEP(__shfl_sync(0xffffffffu, sv, j));
        }
    }

    float inv = 1.f / ssum;
    int g = batch[d];
    float4* sd = (float4*)(g_sums + g * HC) + 2 * lane;
    redAdd4(sd,     make_float4(acc[0] * inv, acc[1] * inv, acc[2] * inv, acc[3] * inv));
    redAdd4(sd + 1, make_float4(acc[4] * inv, acc[5] * inv, acc[6] * inv, acc[7] * inv));
    if (lane == 0) atomicAdd(&g_cnts[g], 1.f);
}

// ---------------- final: (mean + b2) @ lin_w + lin_b --------------------------
__global__ void final_k(const float* __restrict__ b2,
                        const float* __restrict__ lw,
                        const float* __restrict__ lb,
                        float* __restrict__ out) {
    __shared__ float p[HC];
    int g = blockIdx.x;
    float cnt = fmaxf(g_cnts[g], 1.f);
    p[threadIdx.x] = g_sums[g * HC + threadIdx.x] / cnt + b2[threadIdx.x];
    __syncthreads();
    if (threadIdx.x < LL) {
        float acc = lb[threadIdx.x];
#pragma unroll 8
        for (int d = 0; d < HC; d++)
            acc = fmaf(p[d], lw[d * LL + threadIdx.x], acc);
        out[g * LL + threadIdx.x] = acc;
    }
}

// ---------------- launch -------------------------------------------------------
extern "C" void kernel_launch(void* const* d_in, const int* in_sizes, int n_in,
                              void* d_out, int out_size) {
    const float* x      = (const float*)d_in[0];
    const int*   ei     = (const int*)d_in[1];
    const int*   batch  = (const int*)d_in[2];
    const float* W1     = (const float*)d_in[3];
    const float* a_src1 = (const float*)d_in[4];
    const float* a_dst1 = (const float*)d_in[5];
    const float* b1     = (const float*)d_in[6];
    const float* W2     = (const float*)d_in[7];
    const float* a_src2 = (const float*)d_in[8];
    const float* a_dst2 = (const float*)d_in[9];
    const float* b2     = (const float*)d_in[10];
    const float* lin_w  = (const float*)d_in[11];
    const float* lin_b  = (const float*)d_in[12];
    float* out = (float*)d_out;

    const int* src = ei;
    const int* dst = ei + EE;

    static cudaStream_t s_adj = nullptr;
    static cudaEvent_t ev_fork = nullptr, ev_adj = nullptr;
    if (!s_adj) {
        cudaStreamCreateWithFlags(&s_adj, cudaStreamNonBlocking);
        cudaEventCreateWithFlags(&ev_fork, cudaEventDisableTiming);
        cudaEventCreateWithFlags(&ev_adj, cudaEventDisableTiming);
    }

    // fork adjacency build at graph start
    cudaEventRecord(ev_fork, 0);
    cudaStreamWaitEvent(s_adj, ev_fork, 0);
    init_side_k<<<(GG * HC + 255) / 256, 256, 0, s_adj>>>();
    adj_fill<<<(EE / 4 + 255) / 256, 256, 0, s_adj>>>(src, dst);
    cudaEventRecord(ev_adj, s_adj);

    // main stream (concurrent): layer-1 GEMM (+fused logits)
    gemm_k<1><<<(NN + 31) / 32, 256>>>(x, W1, nullptr, a_src1, a_dst1);

    // join: gat1 needs adjacency
    cudaStreamWaitEvent(0, ev_adj, 0);
    gat1_k<<<(NN * 32 + 255) / 256, 256>>>();

    // layer 2 (relu(out1+b1) folded into gemm2 load; logits fused)
    gemm_k<2><<<(NN + 31) / 32, 256>>>(nullptr, W2, b1, a_src2, a_dst2);
    gat2_k<<<(NN * 32 + 255) / 256, 256>>>(batch);

    final_k<<<GG, 256>>>(b2, lin_w, lin_b, out);
}

// round 8
// speedup vs baseline: 1.1263x; 1.0614x over previous
#include <cuda_runtime.h>
#include <cuda_fp16.h>
#include <math.h>

#define NN 10000
#define EE 320000
#define FIN 128
#define HC 256
#define NH1 16
#define NC1 16
#define GG 64
#define LL 10
#define CAP 256            // per-node adjacency bucket capacity (max deg ~60)

typedef unsigned long long u64;

// ---------------- scratch ----------------------------------------------------
__device__ __half g_h1h[NN * HC];    // layer1 features (fp16 gather copy)
__device__ __half g_h2h[NN * HC];    // layer2 features (fp16 gather copy)
__device__ float g_out1[NN * HC];    // layer1 aggregated output (fp32)
__device__ float g_als1[NN * NH1];
__device__ float g_ald1[NN * NH1];
__device__ float g_als2[NN];
__device__ float g_ald2[NN];
__device__ float g_sums[GG * HC];
__device__ float g_cnts[GG];
__device__ int   g_deg[NN];          // bucket fill cursor / final degree
__device__ int   g_adj[NN * CAP];    // bucketed adjacency (src lists per dst)

__device__ __forceinline__ float leaky(float v) { return v >= 0.f ? v : 0.2f * v; }

__device__ __forceinline__ void redAdd4(float4* addr, float4 v) {
    asm volatile("red.global.add.v4.f32 [%0], {%1, %2, %3, %4};"
                 :: "l"(addr), "f"(v.x), "f"(v.y), "f"(v.z), "f"(v.w) : "memory");
}

__device__ __forceinline__ u64 packdup(float w) {
    u64 r; asm("mov.b64 %0, {%1, %1};" : "=l"(r) : "f"(w)); return r;
}
__device__ __forceinline__ void fma2(u64& acc, u64 x, u64 w) {
    asm("fma.rn.f32x2 %0, %1, %2, %0;" : "+l"(acc) : "l"(x), "l"(w));
}
__device__ __forceinline__ float2 unpack2(u64 v) {
    float lo, hi; asm("mov.b64 {%0, %1}, %2;" : "=f"(lo), "=f"(hi) : "l"(v));
    return make_float2(lo, hi);
}

// ---------------- side-stream init -------------------------------------------
__global__ void init_side_k() {
    int i = blockIdx.x * blockDim.x + threadIdx.x;
    if (i < NN) g_deg[i] = 0;
    if (i < GG * HC) g_sums[i] = 0.f;
    if (i < GG) g_cnts[i] = 0.f;
}

// ---------------- bucketed adjacency fill (no count/scan) ---------------------
__global__ void adj_fill(const int* __restrict__ src, const int* __restrict__ dst) {
    int i = blockIdx.x * blockDim.x + threadIdx.x;
    if (i * 4 >= EE) return;
    int4 s4 = ((const int4*)src)[i];
    int4 d4 = ((const int4*)dst)[i];
    int p;
    p = atomicAdd(&g_deg[d4.x], 1); g_adj[d4.x * CAP + p] = s4.x;
    p = atomicAdd(&g_deg[d4.y], 1); g_adj[d4.y * CAP + p] = s4.y;
    p = atomicAdd(&g_deg[d4.z], 1); g_adj[d4.z * CAP + p] = s4.z;
    p = atomicAdd(&g_deg[d4.w], 1); g_adj[d4.w * CAP + p] = s4.w;
}

// ---------------- GEMM + fused logits + fp16 store (R5 inner loop) -----------
template <int LAYER>
__global__ void __launch_bounds__(256) gemm_k(const float* __restrict__ Xin,
                       const float* __restrict__ W,
                       const float* __restrict__ bin,
                       const float* __restrict__ a_src,
                       const float* __restrict__ a_dst) {
    constexpr int K = (LAYER == 1) ? FIN : HC;
    const float* __restrict__ X = (LAYER == 1) ? Xin : g_out1;
    __half* __restrict__ Hout = (LAYER == 1) ? g_h1h : g_h2h;

    __shared__ u64 xst[K * 16];             // [k][row_pair]
    __shared__ float red[8][64];            // layer-2 logit reduction
    float* xs = (float*)xst;

    int row0 = blockIdx.x * 32;
    int col = threadIdx.x;

    for (int i = threadIdx.x; i < 32 * K; i += 256) {
        int r = i & 31, k = i >> 5;
        int row = row0 + r;
        float v = 0.f;
        if (row < NN) {
            v = X[(size_t)row * K + k];
            if (LAYER == 2) v = fmaxf(v + bin[k], 0.f);
        }
        xs[k * 32 + r] = v;
    }
    __syncthreads();

    u64 acc[16];
#pragma unroll
    for (int p = 0; p < 16; p++) acc[p] = 0ull;

#pragma unroll 4
    for (int k = 0; k < K; k++) {
        u64 wp = packdup(W[k * HC + col]);
        const u64* xp = xst + k * 16;
#pragma unroll
        for (int p = 0; p < 16; p++) fma2(acc[p], xp[p], wp);
    }

    float As = a_src[col], Ad = a_dst[col];

#pragma unroll
    for (int p = 0; p < 16; p++) {
        float2 lh = unpack2(acc[p]);
        int r0 = row0 + 2 * p;
        if (r0 < NN)     Hout[(size_t)r0 * HC + col] = __float2half_rn(lh.x);
        if (r0 + 1 < NN) Hout[(size_t)(r0 + 1) * HC + col] = __float2half_rn(lh.y);

        float vs0 = lh.x * As, vd0 = lh.x * Ad;
        float vs1 = lh.y * As, vd1 = lh.y * Ad;

        if (LAYER == 1) {
#pragma unroll
            for (int o = 1; o < 16; o <<= 1) {
                vs0 += __shfl_xor_sync(0xffffffffu, vs0, o);
                vd0 += __shfl_xor_sync(0xffffffffu, vd0, o);
                vs1 += __shfl_xor_sync(0xffffffffu, vs1, o);
                vd1 += __shfl_xor_sync(0xffffffffu, vd1, o);
            }
            if ((col & 15) == 0) {
                int head = col >> 4;
                if (r0 < NN)     { g_als1[r0 * NH1 + head] = vs0; g_ald1[r0 * NH1 + head] = vd0; }
                if (r0 + 1 < NN) { g_als1[(r0 + 1) * NH1 + head] = vs1; g_ald1[(r0 + 1) * NH1 + head] = vd1; }
            }
        } else {
#pragma unroll
            for (int o = 1; o < 32; o <<= 1) {
                vs0 += __shfl_xor_sync(0xffffffffu, vs0, o);
                vd0 += __shfl_xor_sync(0xffffffffu, vd0, o);
                vs1 += __shfl_xor_sync(0xffffffffu, vs1, o);
                vd1 += __shfl_xor_sync(0xffffffffu, vd1, o);
            }
            if ((col & 31) == 0) {
                int w = col >> 5;
                red[w][p * 4 + 0] = vs0;
                red[w][p * 4 + 1] = vd0;
                red[w][p * 4 + 2] = vs1;
                red[w][p * 4 + 3] = vd1;
            }
        }
    }

    if (LAYER == 2) {
        __syncthreads();
        if (threadIdx.x < 64) {
            int t = threadIdx.x;
            float s = 0.f;
#pragma unroll
            for (int w = 0; w < 8; w++) s += red[w][t];
            int p = t >> 2, q = t & 3;
            int r = row0 + 2 * p + (q >> 1);
            if (r < NN) {
                if ((q & 1) == 0) g_als2[r] = s;
                else              g_ald2[r] = s;
            }
        }
    }
}

// ---------------- fused GAT layer 1 (16 heads), fp16 gather, warp per dst -----
__global__ void __launch_bounds__(256) gat1_k() {
    int w = (blockIdx.x * blockDim.x + threadIdx.x) >> 5;
    int lane = threadIdx.x & 31;
    if (w >= NN) return;
    const int d = w;
    const int hh = lane >> 1;            // 8 channels per lane, head = lane>>1

    float ald_h = g_ald1[d * NH1 + hh];
    float wself = __expf(leaky(g_als1[d * NH1 + hh] + ald_h));
    float ssum = wself;

    float acc[8];
    {
        uint4 q = *((const uint4*)(g_h1h + (size_t)d * HC) + lane);
        const __half2* h2 = (const __half2*)&q;
#pragma unroll
        for (int k = 0; k < 4; k++) {
            float2 f = __half22float2(h2[k]);
            acc[2 * k] = wself * f.x;
            acc[2 * k + 1] = wself * f.y;
        }
    }

    int beg = d * CAP;
    int end = beg + g_deg[d];

#define GAT1_STEP(SRC)                                                          \
    {                                                                           \
        int s_ = (SRC);                                                         \
        float we = __expf(leaky(g_als1[s_ * NH1 + hh] + ald_h));                \
        ssum += we;                                                             \
        uint4 q = *((const uint4*)(g_h1h + (size_t)s_ * HC) + lane);            \
        const __half2* h2 = (const __half2*)&q;                                 \
        _Pragma("unroll")                                                       \
        for (int k = 0; k < 4; k++) {                                           \
            float2 f = __half22float2(h2[k]);                                   \
            acc[2 * k]     = fmaf(we, f.x, acc[2 * k]);                         \
            acc[2 * k + 1] = fmaf(we, f.y, acc[2 * k + 1]);                     \
        }                                                                       \
    }

    for (int base = beg; base < end; base += 32) {
        int idx = base + lane;
        int sv = (idx < end) ? g_adj[idx] : 0;
        int n = min(32, end - base);
        if (n == 32) {
#pragma unroll 8
            for (int j = 0; j < 32; j++) GAT1_STEP(__shfl_sync(0xffffffffu, sv, j));
        } else {
            for (int j = 0; j < n; j++) GAT1_STEP(__shfl_sync(0xffffffffu, sv, j));
        }
    }

    float inv = 1.f / ssum;
    float4* od = (float4*)(g_out1 + (size_t)d * HC) + 2 * lane;
    od[0] = make_float4(acc[0] * inv, acc[1] * inv, acc[2] * inv, acc[3] * inv);
    od[1] = make_float4(acc[4] * inv, acc[5] * inv, acc[6] * inv, acc[7] * inv);
}

// ---------------- fused GAT layer 2 (1 head) + mean-pool red ------------------
__global__ void __launch_bounds__(256) gat2_k(const int* __restrict__ batch) {
    int w = (blockIdx.x * blockDim.x + threadIdx.x) >> 5;
    int lane = threadIdx.x & 31;
    if (w >= NN) return;
    const int d = w;

    float ald_d = g_ald2[d];
    float wself = __expf(leaky(g_als2[d] + ald_d));
    float ssum = wself;

    float acc[8];
    {
        uint4 q = *((const uint4*)(g_h2h + (size_t)d * HC) + lane);
        const __half2* h2 = (const __half2*)&q;
#pragma unroll
        for (int k = 0; k < 4; k++) {
            float2 f = __half22float2(h2[k]);
            acc[2 * k] = wself * f.x;
            acc[2 * k + 1] = wself * f.y;
        }
    }

    int beg = d * CAP;
    int end = beg + g_deg[d];

#define GAT2_STEP(SRC)                                                          \
    {                                                                           \
        int s_ = (SRC);                                                         \
        float we = __expf(leaky(g_als2[s_] + ald_d));                           \
        ssum += we;                                                             \
        uint4 q = *((const uint4*)(g_h2h + (size_t)s_ * HC) + lane);            \
        const __half2* h2 = (const __half2*)&q;                                 \
        _Pragma("unroll")                                                       \
        for (int k = 0; k < 4; k++) {                                           \
            float2 f = __half22float2(h2[k]);                                   \
            acc[2 * k]     = fmaf(we, f.x, acc[2 * k]);                         \
            acc[2 * k + 1] = fmaf(we, f.y, acc[2 * k + 1]);                     \
        }                                                                       \
    }

    for (int base = beg; base < end; base += 32) {
        int idx = base + lane;
        int sv = (idx < end) ? g_adj[idx] : 0;
        int n = min(32, end - base);
        if (n == 32) {
#pragma unroll 8
            for (int j = 0; j < 32; j++) GAT2_STEP(__shfl_sync(0xffffffffu, sv, j));
        } else {
            for (int j = 0; j < n; j++) GAT2_STEP(__shfl_sync(0xffffffffu, sv, j));
        }
    }

    float inv = 1.f / ssum;
    int g = batch[d];
    float4* sd = (float4*)(g_sums + g * HC) + 2 * lane;
    redAdd4(sd,     make_float4(acc[0] * inv, acc[1] * inv, acc[2] * inv, acc[3] * inv));
    redAdd4(sd + 1, make_float4(acc[4] * inv, acc[5] * inv, acc[6] * inv, acc[7] * inv));
    if (lane == 0) atomicAdd(&g_cnts[g], 1.f);
}

// ---------------- final: (mean + b2) @ lin_w + lin_b --------------------------
__global__ void final_k(const float* __restrict__ b2,
                        const float* __restrict__ lw,
                        const float* __restrict__ lb,
                        float* __restrict__ out) {
    __shared__ float p[HC];
    int g = blockIdx.x;
    float cnt = fmaxf(g_cnts[g], 1.f);
    p[threadIdx.x] = g_sums[g * HC + threadIdx.x] / cnt + b2[threadIdx.x];
    __syncthreads();
    if (threadIdx.x < LL) {
        float acc = lb[threadIdx.x];
#pragma unroll 8
        for (int d = 0; d < HC; d++)
            acc = fmaf(p[d], lw[d * LL + threadIdx.x], acc);
        out[g * LL + threadIdx.x] = acc;
    }
}

// ---------------- launch -------------------------------------------------------
extern "C" void kernel_launch(void* const* d_in, const int* in_sizes, int n_in,
                              void* d_out, int out_size) {
    const float* x      = (const float*)d_in[0];
    const int*   ei     = (const int*)d_in[1];
    const int*   batch  = (const int*)d_in[2];
    const float* W1     = (const float*)d_in[3];
    const float* a_src1 = (const float*)d_in[4];
    const float* a_dst1 = (const float*)d_in[5];
    const float* b1     = (const float*)d_in[6];
    const float* W2     = (const float*)d_in[7];
    const float* a_src2 = (const float*)d_in[8];
    const float* a_dst2 = (const float*)d_in[9];
    const float* b2     = (const float*)d_in[10];
    const float* lin_w  = (const float*)d_in[11];
    const float* lin_b  = (const float*)d_in[12];
    float* out = (float*)d_out;

    const int* src = ei;
    const int* dst = ei + EE;

    static cudaStream_t s_adj = nullptr;
    static cudaEvent_t ev_fork = nullptr, ev_adj = nullptr;
    if (!s_adj) {
        cudaStreamCreateWithFlags(&s_adj, cudaStreamNonBlocking);
        cudaEventCreateWithFlags(&ev_fork, cudaEventDisableTiming);
        cudaEventCreateWithFlags(&ev_adj, cudaEventDisableTiming);
    }

    // fork adjacency build at graph start
    cudaEventRecord(ev_fork, 0);
    cudaStreamWaitEvent(s_adj, ev_fork, 0);
    init_side_k<<<(GG * HC + 255) / 256, 256, 0, s_adj>>>();
    adj_fill<<<(EE / 4 + 255) / 256, 256, 0, s_adj>>>(src, dst);
    cudaEventRecord(ev_adj, s_adj);

    // main stream (concurrent): layer-1 GEMM (+fused logits)
    gemm_k<1><<<(NN + 31) / 32, 256>>>(x, W1, nullptr, a_src1, a_dst1);

    // join: gat1 needs adjacency
    cudaStreamWaitEvent(0, ev_adj, 0);
    gat1_k<<<(NN * 32 + 255) / 256, 256>>>();

    // layer 2 (relu(out1+b1) folded into gemm2 load; logits fused)
    gemm_k<2><<<(NN + 31) / 32, 256>>>(nullptr, W2, b1, a_src2, a_dst2);
    gat2_k<<<(NN * 32 + 255) / 256, 256>>>(batch);

    final_k<<<GG, 256>>>(b2, lin_w, lin_b, out);
}

// round 9
// speedup vs baseline: 1.9581x; 1.7385x over previous
#include <cuda_runtime.h>
#include <cuda_fp16.h>
#include <math.h>

#define NN 10000
#define EE 320000
#define FIN 128
#define HC 256
#define NH1 16
#define GG 64
#define LL 10
#define CAP 256            // per-node adjacency bucket capacity (max deg ~60)

typedef unsigned int u32;

// ---------------- scratch ----------------------------------------------------
__device__ __half g_h1h[NN * HC];    // layer1 features fp16
__device__ __half g_h2h[NN * HC];    // layer2 features fp16
__device__ float g_out1[NN * HC];    // layer1 aggregated output (fp32)
__device__ __half g_w1t[HC * FIN];   // W1^T fp16 [n][k]
__device__ __half g_w2t[HC * HC];    // W2^T fp16 [n][k]
__device__ float g_als1[NN * NH1];
__device__ float g_ald1[NN * NH1];
__device__ float g_als2[NN];
__device__ float g_ald2[NN];
__device__ float g_sums[GG * HC];
__device__ float g_cnts[GG];
__device__ int   g_deg[NN];
__device__ int   g_adj[NN * CAP];

__device__ __forceinline__ float leaky(float v) { return v >= 0.f ? v : 0.2f * v; }

__device__ __forceinline__ void redAdd4(float4* addr, float4 v) {
    asm volatile("red.global.add.v4.f32 [%0], {%1, %2, %3, %4};"
                 :: "l"(addr), "f"(v.x), "f"(v.y), "f"(v.z), "f"(v.w) : "memory");
}

__device__ __forceinline__ void mma16816(float* c, u32 a0, u32 a1, u32 a2, u32 a3,
                                         u32 b0, u32 b1) {
    asm volatile(
        "mma.sync.aligned.m16n8k16.row.col.f32.f16.f16.f32 "
        "{%0,%1,%2,%3}, {%4,%5,%6,%7}, {%8,%9}, {%0,%1,%2,%3};"
        : "+f"(c[0]), "+f"(c[1]), "+f"(c[2]), "+f"(c[3])
        : "r"(a0), "r"(a1), "r"(a2), "r"(a3), "r"(b0), "r"(b1));
}

// ---------------- side-stream init + adjacency --------------------------------
__global__ void init_side_k() {
    int i = blockIdx.x * blockDim.x + threadIdx.x;
    if (i < NN) g_deg[i] = 0;
    if (i < GG * HC) g_sums[i] = 0.f;
    if (i < GG) g_cnts[i] = 0.f;
}

__global__ void adj_fill(const int* __restrict__ src, const int* __restrict__ dst) {
    int i = blockIdx.x * blockDim.x + threadIdx.x;
    if (i * 4 >= EE) return;
    int4 s4 = ((const int4*)src)[i];
    int4 d4 = ((const int4*)dst)[i];
    int p;
    p = atomicAdd(&g_deg[d4.x], 1); g_adj[d4.x * CAP + p] = s4.x;
    p = atomicAdd(&g_deg[d4.y], 1); g_adj[d4.y * CAP + p] = s4.y;
    p = atomicAdd(&g_deg[d4.z], 1); g_adj[d4.z * CAP + p] = s4.z;
    p = atomicAdd(&g_deg[d4.w], 1); g_adj[d4.w * CAP + p] = s4.w;
}

// ---------------- weight transpose+convert ------------------------------------
__global__ void wconv_k(const float* __restrict__ W1, const float* __restrict__ W2) {
    int i = blockIdx.x * blockDim.x + threadIdx.x;
    if (i < FIN * HC) {               // W1 [128][256] -> w1t [256][128]
        int k = i >> 8, n = i & 255;
        g_w1t[n * FIN + k] = __float2half_rn(W1[i]);
    }
    if (i < HC * HC) {                // W2 [256][256] -> w2t [256][256]
        int k = i >> 8, n = i & 255;
        g_w2t[n * HC + k] = __float2half_rn(W2[i]);
    }
}

// ---------------- tensor-core GEMM: h[N,256] = X[N,K] @ W ---------------------
#define KC 64
#define LDA 72
#define LDB 72

template <int LAYER>
__global__ void __launch_bounds__(256) gemm_mma(const float* __restrict__ Xin,
                                                const float* __restrict__ bin) {
    constexpr int K = (LAYER == 1) ? FIN : HC;
    const float* __restrict__ X = (LAYER == 1) ? Xin : g_out1;
    const __half* __restrict__ Wt = (LAYER == 1) ? g_w1t : g_w2t;
    __half* __restrict__ Hout = (LAYER == 1) ? g_h1h : g_h2h;

    __shared__ __half As[32 * LDA];
    __shared__ __half Ws[256 * LDB];

    int row0 = blockIdx.x * 32;
    int tid = threadIdx.x;
    int warp = tid >> 5, lane = tid & 31;
    int gr = lane >> 2, tg = lane & 3;
    int wr = (warp & 1) * 16;
    int wc = (warp >> 1) * 64;

    float c[8][4];
#pragma unroll
    for (int t = 0; t < 8; t++)
#pragma unroll
        for (int j = 0; j < 4; j++) c[t][j] = 0.f;

    for (int kc0 = 0; kc0 < K; kc0 += KC) {
        // --- load A chunk: 32 rows x 64 cols fp32 -> fp16 (bias+relu for L2) ---
        {
            int r = tid >> 3, cc = (tid & 7) * 8;
            int row = row0 + r;
            float4 v0 = {0, 0, 0, 0}, v1 = {0, 0, 0, 0};
            if (row < NN) {
                const float4* p = (const float4*)(X + (size_t)row * K + kc0 + cc);
                v0 = p[0]; v1 = p[1];
                if (LAYER == 2) {
                    const float4* bb = (const float4*)(bin + kc0 + cc);
                    float4 b0 = bb[0], b1 = bb[1];
                    v0.x = fmaxf(v0.x + b0.x, 0.f); v0.y = fmaxf(v0.y + b0.y, 0.f);
                    v0.z = fmaxf(v0.z + b0.z, 0.f); v0.w = fmaxf(v0.w + b0.w, 0.f);
                    v1.x = fmaxf(v1.x + b1.x, 0.f); v1.y = fmaxf(v1.y + b1.y, 0.f);
                    v1.z = fmaxf(v1.z + b1.z, 0.f); v1.w = fmaxf(v1.w + b1.w, 0.f);
                }
            }
            __half2 h0 = __floats2half2_rn(v0.x, v0.y);
            __half2 h1 = __floats2half2_rn(v0.z, v0.w);
            __half2 h2 = __floats2half2_rn(v1.x, v1.y);
            __half2 h3 = __floats2half2_rn(v1.z, v1.w);
            uint4 pk;
            pk.x = *(u32*)&h0; pk.y = *(u32*)&h1; pk.z = *(u32*)&h2; pk.w = *(u32*)&h3;
            *(uint4*)(As + r * LDA + cc) = pk;     // 144r + 16*(cc/8): 16B aligned
        }
        // --- load W chunk: 256 n-rows x 64 k-cols fp16 ---
        {
            int cc = (tid & 7) * 8;
#pragma unroll
            for (int pass = 0; pass < 8; pass++) {
                int n = pass * 32 + (tid >> 3);
                uint4 v = *(const uint4*)(Wt + (size_t)n * K + kc0 + cc);
                *(uint4*)(Ws + n * LDB + cc) = v;
            }
        }
        __syncthreads();

#pragma unroll
        for (int ks = 0; ks < KC; ks += 16) {
            u32 a0 = *(u32*)&As[(wr + gr) * LDA + ks + tg * 2];
            u32 a1 = *(u32*)&As[(wr + gr + 8) * LDA + ks + tg * 2];
            u32 a2 = *(u32*)&As[(wr + gr) * LDA + ks + tg * 2 + 8];
            u32 a3 = *(u32*)&As[(wr + gr + 8) * LDA + ks + tg * 2 + 8];
#pragma unroll
            for (int t = 0; t < 8; t++) {
                int n = wc + t * 8 + gr;
                u32 b0 = *(u32*)&Ws[n * LDB + ks + tg * 2];
                u32 b1 = *(u32*)&Ws[n * LDB + ks + tg * 2 + 8];
                mma16816(c[t], a0, a1, a2, a3, b0, b1);
            }
        }
        __syncthreads();
    }

    // --- epilogue: store fp16 h ---
    int r_a = row0 + wr + gr;
    int r_b = r_a + 8;
#pragma unroll
    for (int t = 0; t < 8; t++) {
        int col = wc + t * 8 + tg * 2;
        if (r_a < NN) {
            __half2 hv = __floats2half2_rn(c[t][0], c[t][1]);
            *(u32*)&Hout[(size_t)r_a * HC + col] = *(u32*)&hv;
        }
        if (r_b < NN) {
            __half2 hv = __floats2half2_rn(c[t][2], c[t][3]);
            *(u32*)&Hout[(size_t)r_b * HC + col] = *(u32*)&hv;
        }
    }
}

// ---------------- attention logits (fp16 h) ------------------------------------
__global__ void attn1_k(const float* __restrict__ a_src, const float* __restrict__ a_dst) {
    int idx = blockIdx.x * blockDim.x + threadIdx.x;
    if (idx >= NN * NH1) return;
    int node = idx >> 4, hd = idx & 15;
    const uint4* p = (const uint4*)(g_h1h + (size_t)node * HC + hd * 16);
    uint4 q0 = p[0], q1 = p[1];
    const __half2* h2a = (const __half2*)&q0;
    const __half2* h2b = (const __half2*)&q1;
    const float* as = a_src + hd * 16;
    const float* ad = a_dst + hd * 16;
    float s1 = 0.f, s2 = 0.f;
#pragma unroll
    for (int k = 0; k < 4; k++) {
        float2 f = __half22float2(h2a[k]);
        s1 = fmaf(f.x, as[2 * k], fmaf(f.y, as[2 * k + 1], s1));
        s2 = fmaf(f.x, ad[2 * k], fmaf(f.y, ad[2 * k + 1], s2));
    }
#pragma unroll
    for (int k = 0; k < 4; k++) {
        float2 f = __half22float2(h2b[k]);
        s1 = fmaf(f.x, as[8 + 2 * k], fmaf(f.y, as[8 + 2 * k + 1], s1));
        s2 = fmaf(f.x, ad[8 + 2 * k], fmaf(f.y, ad[8 + 2 * k + 1], s2));
    }
    g_als1[idx] = s1;
    g_ald1[idx] = s2;
}

__global__ void attn2_k(const float* __restrict__ a_src, const float* __restrict__ a_dst) {
    int w = (blockIdx.x * blockDim.x + threadIdx.x) >> 5;
    int lane = threadIdx.x & 31;
    if (w >= NN) return;
    uint4 q = *((const uint4*)(g_h2h + (size_t)w * HC) + lane);
    const __half2* h2 = (const __half2*)&q;
    const float* as = a_src + lane * 8;
    const float* ad = a_dst + lane * 8;
    float s1 = 0.f, s2 = 0.f;
#pragma unroll
    for (int k = 0; k < 4; k++) {
        float2 f = __half22float2(h2[k]);
        s1 = fmaf(f.x, as[2 * k], fmaf(f.y, as[2 * k + 1], s1));
        s2 = fmaf(f.x, ad[2 * k], fmaf(f.y, ad[2 * k + 1], s2));
    }
#pragma unroll
    for (int o = 16; o; o >>= 1) {
        s1 += __shfl_xor_sync(0xffffffffu, s1, o);
        s2 += __shfl_xor_sync(0xffffffffu, s2, o);
    }
    if (lane == 0) { g_als2[w] = s1; g_ald2[w] = s2; }
}

// ---------------- fused GAT layer 1 (16 heads), fp16 gather, warp per dst -----
__global__ void __launch_bounds__(256) gat1_k() {
    int w = (blockIdx.x * blockDim.x + threadIdx.x) >> 5;
    int lane = threadIdx.x & 31;
    if (w >= NN) return;
    const int d = w;
    const int hh = lane >> 1;

    float ald_h = g_ald1[d * NH1 + hh];
    float wself = __expf(leaky(g_als1[d * NH1 + hh] + ald_h));
    float ssum = wself;

    float acc[8];
    {
        uint4 q = *((const uint4*)(g_h1h + (size_t)d * HC) + lane);
        const __half2* h2 = (const __half2*)&q;
#pragma unroll
        for (int k = 0; k < 4; k++) {
            float2 f = __half22float2(h2[k]);
            acc[2 * k] = wself * f.x;
            acc[2 * k + 1] = wself * f.y;
        }
    }

    int beg = d * CAP;
    int end = beg + g_deg[d];

#define GAT1_STEP(SRC)                                                          \
    {                                                                           \
        int s_ = (SRC);                                                         \
        float we = __expf(leaky(g_als1[s_ * NH1 + hh] + ald_h));                \
        ssum += we;                                                             \
        uint4 q = *((const uint4*)(g_h1h + (size_t)s_ * HC) + lane);            \
        const __half2* h2 = (const __half2*)&q;                                 \
        _Pragma("unroll")                                                       \
        for (int k = 0; k < 4; k++) {                                           \
            float2 f = __half22float2(h2[k]);                                   \
            acc[2 * k]     = fmaf(we, f.x, acc[2 * k]);                         \
            acc[2 * k + 1] = fmaf(we, f.y, acc[2 * k + 1]);                     \
        }                                                                       \
    }

    for (int base = beg; base < end; base += 32) {
        int idx = base + lane;
        int sv = (idx < end) ? g_adj[idx] : 0;
        int n = min(32, end - base);
        if (n == 32) {
#pragma unroll 8
            for (int j = 0; j < 32; j++) GAT1_STEP(__shfl_sync(0xffffffffu, sv, j));
        } else {
            for (int j = 0; j < n; j++) GAT1_STEP(__shfl_sync(0xffffffffu, sv, j));
        }
    }

    float inv = 1.f / ssum;
    float4* od = (float4*)(g_out1 + (size_t)d * HC) + 2 * lane;
    od[0] = make_float4(acc[0] * inv, acc[1] * inv, acc[2] * inv, acc[3] * inv);
    od[1] = make_float4(acc[4] * inv, acc[5] * inv, acc[6] * inv, acc[7] * inv);
}

// ---------------- fused GAT layer 2 (1 head) + mean-pool red ------------------
__global__ void __launch_bounds__(256) gat2_k(const int* __restrict__ batch) {
    int w = (blockIdx.x * blockDim.x + threadIdx.x) >> 5;
    int lane = threadIdx.x & 31;
    if (w >= NN) return;
    const int d = w;

    float ald_d = g_ald2[d];
    float wself = __expf(leaky(g_als2[d] + ald_d));
    float ssum = wself;

    float acc[8];
    {
        uint4 q = *((const uint4*)(g_h2h + (size_t)d * HC) + lane);
        const __half2* h2 = (const __half2*)&q;
#pragma unroll
        for (int k = 0; k < 4; k++) {
            float2 f = __half22float2(h2[k]);
            acc[2 * k] = wself * f.x;
            acc[2 * k + 1] = wself * f.y;
        }
    }

    int beg = d * CAP;
    int end = beg + g_deg[d];

#define GAT2_STEP(SRC)                                                          \
    {                                                                           \
        int s_ = (SRC);                                                         \
        float we = __expf(leaky(g_als2[s_] + ald_d));                           \
        ssum += we;                                                             \
        uint4 q = *((const uint4*)(g_h2h + (size_t)s_ * HC) + lane);            \
        const __half2* h2 = (const __half2*)&q;                                 \
        _Pragma("unroll")                                                       \
        for (int k = 0; k < 4; k++) {                                           \
            float2 f = __half22float2(h2[k]);                                   \
            acc[2 * k]     = fmaf(we, f.x, acc[2 * k]);                         \
            acc[2 * k + 1] = fmaf(we, f.y, acc[2 * k + 1]);                     \
        }                                                                       \
    }

    for (int base = beg; base < end; base += 32) {
        int idx = base + lane;
        int sv = (idx < end) ? g_adj[idx] : 0;
        int n = min(32, end - base);
        if (n == 32) {
#pragma unroll 8
            for (int j = 0; j < 32; j++) GAT2_STEP(__shfl_sync(0xffffffffu, sv, j));
        } else {
            for (int j = 0; j < n; j++) GAT2_STEP(__shfl_sync(0xffffffffu, sv, j));
        }
    }

    float inv = 1.f / ssum;
    int g = batch[d];
    float4* sd = (float4*)(g_sums + g * HC) + 2 * lane;
    redAdd4(sd,     make_float4(acc[0] * inv, acc[1] * inv, acc[2] * inv, acc[3] * inv));
    redAdd4(sd + 1, make_float4(acc[4] * inv, acc[5] * inv, acc[6] * inv, acc[7] * inv));
    if (lane == 0) atomicAdd(&g_cnts[g], 1.f);
}

// ---------------- final: (mean + b2) @ lin_w + lin_b --------------------------
__global__ void final_k(const float* __restrict__ b2,
                        const float* __restrict__ lw,
                        const float* __restrict__ lb,
                        float* __restrict__ out) {
    __shared__ float p[HC];
    int g = blockIdx.x;
    float cnt = fmaxf(g_cnts[g], 1.f);
    p[threadIdx.x] = g_sums[g * HC + threadIdx.x] / cnt + b2[threadIdx.x];
    __syncthreads();
    if (threadIdx.x < LL) {
        float acc = lb[threadIdx.x];
#pragma unroll 8
        for (int d = 0; d < HC; d++)
            acc = fmaf(p[d], lw[d * LL + threadIdx.x], acc);
        out[g * LL + threadIdx.x] = acc;
    }
}

// ---------------- launch -------------------------------------------------------
extern "C" void kernel_launch(void* const* d_in, const int* in_sizes, int n_in,
                              void* d_out, int out_size) {
    const float* x      = (const float*)d_in[0];
    const int*   ei     = (const int*)d_in[1];
    const int*   batch  = (const int*)d_in[2];
    const float* W1     = (const float*)d_in[3];
    const float* a_src1 = (const float*)d_in[4];
    const float* a_dst1 = (const float*)d_in[5];
    const float* b1     = (const float*)d_in[6];
    const float* W2     = (const float*)d_in[7];
    const float* a_src2 = (const float*)d_in[8];
    const float* a_dst2 = (const float*)d_in[9];
    const float* b2     = (const float*)d_in[10];
    const float* lin_w  = (const float*)d_in[11];
    const float* lin_b  = (const float*)d_in[12];
    float* out = (float*)d_out;

    const int* src = ei;
    const int* dst = ei + EE;

    static cudaStream_t s_adj = nullptr;
    static cudaEvent_t ev_fork = nullptr, ev_adj = nullptr;
    if (!s_adj) {
        cudaStreamCreateWithFlags(&s_adj, cudaStreamNonBlocking);
        cudaEventCreateWithFlags(&ev_fork, cudaEventDisableTiming);
        cudaEventCreateWithFlags(&ev_adj, cudaEventDisableTiming);
    }

    // fork adjacency build at graph start
    cudaEventRecord(ev_fork, 0);
    cudaStreamWaitEvent(s_adj, ev_fork, 0);
    init_side_k<<<(GG * HC + 255) / 256, 256, 0, s_adj>>>();
    adj_fill<<<(EE / 4 + 255) / 256, 256, 0, s_adj>>>(src, dst);
    cudaEventRecord(ev_adj, s_adj);

    // main stream: weight convert, layer-1 GEMM + logits
    wconv_k<<<(HC * HC + 255) / 256, 256>>>(W1, W2);
    gemm_mma<1><<<(NN + 31) / 32, 256>>>(x, nullptr);
    attn1_k<<<(NN * NH1 + 255) / 256, 256>>>(a_src1, a_dst1);

    // join: gat1 needs adjacency
    cudaStreamWaitEvent(0, ev_adj, 0);
    gat1_k<<<(NN * 32 + 255) / 256, 256>>>();

    // layer 2 (relu(out1+b1) folded into gemm2 A-load)
    gemm_mma<2><<<(NN + 31) / 32, 256>>>(nullptr, b1);
    attn2_k<<<(NN * 32 + 255) / 256, 256>>>(a_src2, a_dst2);
    gat2_k<<<(NN * 32 + 255) / 256, 256>>>(batch);

    final_k<<<GG, 256>>>(b2, lin_w, lin_b, out);
}

// round 10
// speedup vs baseline: 2.1078x; 1.0765x over previous
#include <cuda_runtime.h>
#include <cuda_fp16.h>
#include <math.h>

#define NN 10000
#define EE 320000
#define FIN 128
#define HC 256
#define NH1 16
#define GG 64
#define LL 10
#define CAP 256

typedef unsigned int u32;

// ---------------- scratch ----------------------------------------------------
__device__ __half g_h1h[NN * HC];
__device__ __half g_h2h[NN * HC];
__device__ float g_out1[NN * HC];
__device__ __half g_w1t[HC * FIN];   // W1^T fp16 [n][k]
__device__ __half g_w2t[HC * HC];    // W2^T fp16 [n][k]
__device__ float g_als1[NN * NH1];
__device__ float g_ald1[NN * NH1];
__device__ float g_als2[NN];
__device__ float g_ald2[NN];
__device__ float g_sums[GG * HC];
__device__ float g_cnts[GG];
__device__ int   g_deg[NN];
__device__ int   g_adj[NN * CAP];

__device__ __forceinline__ float leaky(float v) { return v >= 0.f ? v : 0.2f * v; }

__device__ __forceinline__ void redAdd4(float4* addr, float4 v) {
    asm volatile("red.global.add.v4.f32 [%0], {%1, %2, %3, %4};"
                 :: "l"(addr), "f"(v.x), "f"(v.y), "f"(v.z), "f"(v.w) : "memory");
}

__device__ __forceinline__ void mma16816(float* c, u32 a0, u32 a1, u32 a2, u32 a3,
                                         u32 b0, u32 b1) {
    asm volatile(
        "mma.sync.aligned.m16n8k16.row.col.f32.f16.f16.f32 "
        "{%0,%1,%2,%3}, {%4,%5,%6,%7}, {%8,%9}, {%0,%1,%2,%3};"
        : "+f"(c[0]), "+f"(c[1]), "+f"(c[2]), "+f"(c[3])
        : "r"(a0), "r"(a1), "r"(a2), "r"(a3), "r"(b0), "r"(b1));
}

__device__ __forceinline__ float red4(float v) {   // sum over 4-lane group
    v += __shfl_down_sync(0xffffffffu, v, 1);
    v += __shfl_down_sync(0xffffffffu, v, 2);
    return v;
}

// ---------------- side-stream init + adjacency --------------------------------
__global__ void init_side_k() {
    int i = blockIdx.x * blockDim.x + threadIdx.x;
    if (i < NN) g_deg[i] = 0;
    if (i < GG * HC) g_sums[i] = 0.f;
    if (i < GG) g_cnts[i] = 0.f;
}

__global__ void adj_fill(const int* __restrict__ src, const int* __restrict__ dst) {
    int i = blockIdx.x * blockDim.x + threadIdx.x;
    if (i * 4 >= EE) return;
    int4 s4 = ((const int4*)src)[i];
    int4 d4 = ((const int4*)dst)[i];
    int p;
    p = atomicAdd(&g_deg[d4.x], 1); g_adj[d4.x * CAP + p] = s4.x;
    p = atomicAdd(&g_deg[d4.y], 1); g_adj[d4.y * CAP + p] = s4.y;
    p = atomicAdd(&g_deg[d4.z], 1); g_adj[d4.z * CAP + p] = s4.z;
    p = atomicAdd(&g_deg[d4.w], 1); g_adj[d4.w * CAP + p] = s4.w;
}

// ---------------- weight transpose+convert ------------------------------------
__global__ void wconv_k(const float* __restrict__ W1, const float* __restrict__ W2) {
    int i = blockIdx.x * blockDim.x + threadIdx.x;
    if (i < FIN * HC) {
        int k = i >> 8, n = i & 255;
        g_w1t[n * FIN + k] = __float2half_rn(W1[i]);
    }
    if (i < HC * HC) {
        int k = i >> 8, n = i & 255;
        g_w2t[n * HC + k] = __float2half_rn(W2[i]);
    }
}

// ---------------- tensor-core GEMM + fused logits ------------------------------
// block: 16 rows x 256 cols, 256 threads, warp w -> cols [32w, 32w+32)
#define KC 64
#define LDA 72
#define LDB 72

template <int LAYER>
__global__ void __launch_bounds__(256) gemm_mma(const float* __restrict__ Xin,
                                                const float* __restrict__ bin,
                                                const float* __restrict__ a_src,
                                                const float* __restrict__ a_dst) {
    constexpr int K = (LAYER == 1) ? FIN : HC;
    const float* __restrict__ X = (LAYER == 1) ? Xin : g_out1;
    const __half* __restrict__ Wt = (LAYER == 1) ? g_w1t : g_w2t;
    __half* __restrict__ Hout = (LAYER == 1) ? g_h1h : g_h2h;

    __shared__ __half As[16 * LDA];
    __shared__ __half Ws[256 * LDB];
    __shared__ float red_s[16][8];
    __shared__ float red_d[16][8];

    int row0 = blockIdx.x * 16;          // NN % 16 == 0: no guards
    int tid = threadIdx.x;
    int warp = tid >> 5, lane = tid & 31;
    int gr = lane >> 2, tg = lane & 3;
    int wc = warp * 32;

    float c[4][4];
#pragma unroll
    for (int t = 0; t < 4; t++)
#pragma unroll
        for (int j = 0; j < 4; j++) c[t][j] = 0.f;

    for (int kc0 = 0; kc0 < K; kc0 += KC) {
        // --- A chunk: 16 rows x 64 cols; thread: row=tid>>4, 4 floats ---
        {
            int r = tid >> 4, cc = (tid & 15) * 4;
            const float4* p = (const float4*)(X + (size_t)(row0 + r) * K + kc0 + cc);
            float4 v = p[0];
            if (LAYER == 2) {
                float4 b = *(const float4*)(bin + kc0 + cc);
                v.x = fmaxf(v.x + b.x, 0.f); v.y = fmaxf(v.y + b.y, 0.f);
                v.z = fmaxf(v.z + b.z, 0.f); v.w = fmaxf(v.w + b.w, 0.f);
            }
            __half2 h0 = __floats2half2_rn(v.x, v.y);
            __half2 h1 = __floats2half2_rn(v.z, v.w);
            uint2 pk; pk.x = *(u32*)&h0; pk.y = *(u32*)&h1;
            *(uint2*)(As + r * LDA + cc) = pk;
        }
        // --- W chunk: 256 n-rows x 64 k ---
        {
            int cc = (tid & 7) * 8;
#pragma unroll
            for (int pass = 0; pass < 8; pass++) {
                int n = pass * 32 + (tid >> 3);
                uint4 v = *(const uint4*)(Wt + (size_t)n * K + kc0 + cc);
                *(uint4*)(Ws + n * LDB + cc) = v;
            }
        }
        __syncthreads();

#pragma unroll
        for (int ks = 0; ks < KC; ks += 16) {
            u32 a0 = *(u32*)&As[gr * LDA + ks + tg * 2];
            u32 a1 = *(u32*)&As[(gr + 8) * LDA + ks + tg * 2];
            u32 a2 = *(u32*)&As[gr * LDA + ks + tg * 2 + 8];
            u32 a3 = *(u32*)&As[(gr + 8) * LDA + ks + tg * 2 + 8];
#pragma unroll
            for (int t = 0; t < 4; t++) {
                int n = wc + t * 8 + gr;
                u32 b0 = *(u32*)&Ws[n * LDB + ks + tg * 2];
                u32 b1 = *(u32*)&Ws[n * LDB + ks + tg * 2 + 8];
                mma16816(c[t], a0, a1, a2, a3, b0, b1);
            }
        }
        __syncthreads();
    }

    int r_a = row0 + gr;
    int r_b = r_a + 8;

    // --- store h fp16 + gather logit pieces ---
    float vsa[4], vda[4], vsb[4], vdb[4];
#pragma unroll
    for (int t = 0; t < 4; t++) {
        int col = wc + t * 8 + tg * 2;
        __half2 ha = __floats2half2_rn(c[t][0], c[t][1]);
        *(u32*)&Hout[(size_t)r_a * HC + col] = *(u32*)&ha;
        __half2 hb = __floats2half2_rn(c[t][2], c[t][3]);
        *(u32*)&Hout[(size_t)r_b * HC + col] = *(u32*)&hb;

        float as0 = a_src[col], as1 = a_src[col + 1];
        float ad0 = a_dst[col], ad1 = a_dst[col + 1];
        vsa[t] = c[t][0] * as0 + c[t][1] * as1;
        vda[t] = c[t][0] * ad0 + c[t][1] * ad1;
        vsb[t] = c[t][2] * as0 + c[t][3] * as1;
        vdb[t] = c[t][2] * ad0 + c[t][3] * ad1;
    }

    if (LAYER == 1) {
        // head h0 = 2*warp (t=0,1), h1 = 2*warp+1 (t=2,3); reduce over tg lanes
        float h0sa = red4(vsa[0] + vsa[1]), h1sa = red4(vsa[2] + vsa[3]);
        float h0da = red4(vda[0] + vda[1]), h1da = red4(vda[2] + vda[3]);
        float h0sb = red4(vsb[0] + vsb[1]), h1sb = red4(vsb[2] + vsb[3]);
        float h0db = red4(vdb[0] + vdb[1]), h1db = red4(vdb[2] + vdb[3]);
        if (tg == 0) {
            int h0 = 2 * warp, h1 = h0 + 1;
            g_als1[r_a * NH1 + h0] = h0sa; g_als1[r_a * NH1 + h1] = h1sa;
            g_ald1[r_a * NH1 + h0] = h0da; g_ald1[r_a * NH1 + h1] = h1da;
            g_als1[r_b * NH1 + h0] = h0sb; g_als1[r_b * NH1 + h1] = h1sb;
            g_ald1[r_b * NH1 + h0] = h0db; g_ald1[r_b * NH1 + h1] = h1db;
        }
    } else {
        float sa = red4(vsa[0] + vsa[1] + vsa[2] + vsa[3]);
        float da = red4(vda[0] + vda[1] + vda[2] + vda[3]);
        float sb = red4(vsb[0] + vsb[1] + vsb[2] + vsb[3]);
        float db = red4(vdb[0] + vdb[1] + vdb[2] + vdb[3]);
        if (tg == 0) {
            red_s[gr][warp] = sa; red_s[gr + 8][warp] = sb;
            red_d[gr][warp] = da; red_d[gr + 8][warp] = db;
        }
        __syncthreads();
        if (tid < 32) {
            int row = tid >> 1, sel = tid & 1;
            const float (*rp)[8] = sel ? red_d : red_s;
            float s = 0.f;
#pragma unroll
            for (int w = 0; w < 8; w++) s += rp[row][w];
            if (sel) g_ald2[row0 + row] = s;
            else     g_als2[row0 + row] = s;
        }
    }
}

// ---------------- fused GAT layer 1 (16 heads), fp16 gather, warp per dst -----
__global__ void __launch_bounds__(256) gat1_k() {
    int w = (blockIdx.x * blockDim.x + threadIdx.x) >> 5;
    int lane = threadIdx.x & 31;
    if (w >= NN) return;
    const int d = w;
    const int hh = lane >> 1;

    float ald_h = g_ald1[d * NH1 + hh];
    float wself = __expf(leaky(g_als1[d * NH1 + hh] + ald_h));
    float ssum = wself;

    float acc[8];
    {
        uint4 q = *((const uint4*)(g_h1h + (size_t)d * HC) + lane);
        const __half2* h2 = (const __half2*)&q;
#pragma unroll
        for (int k = 0; k < 4; k++) {
            float2 f = __half22float2(h2[k]);
            acc[2 * k] = wself * f.x;
            acc[2 * k + 1] = wself * f.y;
        }
    }

    int beg = d * CAP;
    int end = beg + g_deg[d];

#define GAT1_STEP(SRC)                                                          \
    {                                                                           \
        int s_ = (SRC);                                                         \
        float we = __expf(leaky(g_als1[s_ * NH1 + hh] + ald_h));                \
        ssum += we;                                                             \
        uint4 q = *((const uint4*)(g_h1h + (size_t)s_ * HC) + lane);            \
        const __half2* h2 = (const __half2*)&q;                                 \
        _Pragma("unroll")                                                       \
        for (int k = 0; k < 4; k++) {                                           \
            float2 f = __half22float2(h2[k]);                                   \
            acc[2 * k]     = fmaf(we, f.x, acc[2 * k]);                         \
            acc[2 * k + 1] = fmaf(we, f.y, acc[2 * k + 1]);                     \
        }                                                                       \
    }

    for (int base = beg; base < end; base += 32) {
        int idx = base + lane;
        int sv = (idx < end) ? g_adj[idx] : 0;
        int n = min(32, end - base);
        if (n == 32) {
#pragma unroll 8
            for (int j = 0; j < 32; j++) GAT1_STEP(__shfl_sync(0xffffffffu, sv, j));
        } else {
            for (int j = 0; j < n; j++) GAT1_STEP(__shfl_sync(0xffffffffu, sv, j));
        }
    }

    float inv = 1.f / ssum;
    float4* od = (float4*)(g_out1 + (size_t)d * HC) + 2 * lane;
    od[0] = make_float4(acc[0] * inv, acc[1] * inv, acc[2] * inv, acc[3] * inv);
    od[1] = make_float4(acc[4] * inv, acc[5] * inv, acc[6] * inv, acc[7] * inv);
}

// ---------------- fused GAT layer 2 (1 head) + mean-pool red ------------------
__global__ void __launch_bounds__(256) gat2_k(const int* __restrict__ batch) {
    int w = (blockIdx.x * blockDim.x + threadIdx.x) >> 5;
    int lane = threadIdx.x & 31;
    if (w >= NN) return;
    const int d = w;

    float ald_d = g_ald2[d];
    float wself = __expf(leaky(g_als2[d] + ald_d));
    float ssum = wself;

    float acc[8];
    {
        uint4 q = *((const uint4*)(g_h2h + (size_t)d * HC) + lane);
        const __half2* h2 = (const __half2*)&q;
#pragma unroll
        for (int k = 0; k < 4; k++) {
            float2 f = __half22float2(h2[k]);
            acc[2 * k] = wself * f.x;
            acc[2 * k + 1] = wself * f.y;
        }
    }

    int beg = d * CAP;
    int end = beg + g_deg[d];

#define GAT2_STEP(SRC)                                                          \
    {                                                                           \
        int s_ = (SRC);                                                         \
        float we = __expf(leaky(g_als2[s_] + ald_d));                           \
        ssum += we;                                                             \
        uint4 q = *((const uint4*)(g_h2h + (size_t)s_ * HC) + lane);            \
        const __half2* h2 = (const __half2*)&q;                                 \
        _Pragma("unroll")                                                       \
        for (int k = 0; k < 4; k++) {                                           \
            float2 f = __half22float2(h2[k]);                                   \
            acc[2 * k]     = fmaf(we, f.x, acc[2 * k]);                         \
            acc[2 * k + 1] = fmaf(we, f.y, acc[2 * k + 1]);                     \
        }                                                                       \
    }

    for (int base = beg; base < end; base += 32) {
        int idx = base + lane;
        int sv = (idx < end) ? g_adj[idx] : 0;
        int n = min(32, end - base);
        if (n == 32) {
#pragma unroll 8
            for (int j = 0; j < 32; j++) GAT2_STEP(__shfl_sync(0xffffffffu, sv, j));
        } else {
            for (int j = 0; j < n; j++) GAT2_STEP(__shfl_sync(0xffffffffu, sv, j));
        }
    }

    float inv = 1.f / ssum;
    int g = batch[d];
    float4* sd = (float4*)(g_sums + g * HC) + 2 * lane;
    redAdd4(sd,     make_float4(acc[0] * inv, acc[1] * inv, acc[2] * inv, acc[3] * inv));
    redAdd4(sd + 1, make_float4(acc[4] * inv, acc[5] * inv, acc[6] * inv, acc[7] * inv));
    if (lane == 0) atomicAdd(&g_cnts[g], 1.f);
}

// ---------------- final: (mean + b2) @ lin_w + lin_b --------------------------
__global__ void final_k(const float* __restrict__ b2,
                        const float* __restrict__ lw,
                        const float* __restrict__ lb,
                        float* __restrict__ out) {
    __shared__ float p[HC];
    int g = blockIdx.x;
    float cnt = fmaxf(g_cnts[g], 1.f);
    p[threadIdx.x] = g_sums[g * HC + threadIdx.x] / cnt + b2[threadIdx.x];
    __syncthreads();
    if (threadIdx.x < LL) {
        float acc = lb[threadIdx.x];
#pragma unroll 8
        for (int d = 0; d < HC; d++)
            acc = fmaf(p[d], lw[d * LL + threadIdx.x], acc);
        out[g * LL + threadIdx.x] = acc;
    }
}

// ---------------- launch -------------------------------------------------------
extern "C" void kernel_launch(void* const* d_in, const int* in_sizes, int n_in,
                              void* d_out, int out_size) {
    const float* x      = (const float*)d_in[0];
    const int*   ei     = (const int*)d_in[1];
    const int*   batch  = (const int*)d_in[2];
    const float* W1     = (const float*)d_in[3];
    const float* a_src1 = (const float*)d_in[4];
    const float* a_dst1 = (const float*)d_in[5];
    const float* b1     = (const float*)d_in[6];
    const float* W2     = (const float*)d_in[7];
    const float* a_src2 = (const float*)d_in[8];
    const float* a_dst2 = (const float*)d_in[9];
    const float* b2     = (const float*)d_in[10];
    const float* lin_w  = (const float*)d_in[11];
    const float* lin_b  = (const float*)d_in[12];
    float* out = (float*)d_out;

    const int* src = ei;
    const int* dst = ei + EE;

    static cudaStream_t s_adj = nullptr;
    static cudaEvent_t ev_fork = nullptr, ev_adj = nullptr;
    if (!s_adj) {
        cudaStreamCreateWithFlags(&s_adj, cudaStreamNonBlocking);
        cudaEventCreateWithFlags(&ev_fork, cudaEventDisableTiming);
        cudaEventCreateWithFlags(&ev_adj, cudaEventDisableTiming);
    }

    // fork adjacency build at graph start
    cudaEventRecord(ev_fork, 0);
    cudaStreamWaitEvent(s_adj, ev_fork, 0);
    init_side_k<<<(GG * HC + 255) / 256, 256, 0, s_adj>>>();
    adj_fill<<<(EE / 4 + 255) / 256, 256, 0, s_adj>>>(src, dst);
    cudaEventRecord(ev_adj, s_adj);

    // main stream: weight convert, layer-1 GEMM (+fused logits)
    wconv_k<<<(HC * HC + 255) / 256, 256>>>(W1, W2);
    gemm_mma<1><<<NN / 16, 256>>>(x, nullptr, a_src1, a_dst1);

    // join: gat1 needs adjacency
    cudaStreamWaitEvent(0, ev_adj, 0);
    gat1_k<<<(NN * 32 + 255) / 256, 256>>>();

    // layer 2 (relu(out1+b1) folded into gemm2 A-load; logits fused)
    gemm_mma<2><<<NN / 16, 256>>>(nullptr, b1, a_src2, a_dst2);
    gat2_k<<<(NN * 32 + 255) / 256, 256>>>(batch);

    final_k<<<GG, 256>>>(b2, lin_w, lin_b, out);
}